// round 11
// baseline (speedup 1.0000x reference)
#include <cuda_runtime.h>
#include <math.h>

#define NNODES 1024
#define FD 64
#define MAXB 4
#define GDIMS 16                 // dims per privatization group
#define NGRP  (FD / GDIMS)       // 4
#define CHUNK 2048               // flows per block

// ---- scratch (no allocations allowed; statically zero-initialized) ----
// INVARIANT: g_node and g_adj are all-zero at every kernel_launch entry.
// k_nodeproc re-zeroes g_node after reading; k_attn re-zeroes g_adj after
// reading. So the invariant is restored by the end of every launch.
__device__ float    g_node[MAXB * NNODES * FD];          // scatter accumulator
__device__ float    g_Wh  [MAXB * NNODES * FD];          // Wh = normalize(node) @ W
__device__ float    g_f1  [MAXB * NNODES];
__device__ float    g_f2  [MAXB * NNODES];
__device__ unsigned g_adj [MAXB * NNODES * (NNODES/32)]; // adjacency bitmask

// ------------------------------------------------------------------
// K1: privatized scatter. Block = (batch, dim-group of 16, chunk of
// 2048 flows). Accumulate into 64KB smem [dim][node] (dim-major ->
// smem-atomic bank = node%32, random per warp), then flush with
// red.global.add.v4 (skip exact-zero groups). Adjacency atomicOr is
// spread evenly: each block covers CHUNK/NGRP = 512 flows.
// Global atomic traffic: 67MB -> ~16MB total.
// ------------------------------------------------------------------
__global__ void k_scatter(const float4* __restrict__ ff,
                          const int* __restrict__ src,
                          const int* __restrict__ dst,
                          int B, int S) {
    extern __shared__ float sacc[];          // GDIMS * NNODES floats = 64KB
    int tid = threadIdx.x;
    int chunksPerBatch = S / CHUNK;          // 8
    int blocksPerBatch = NGRP * chunksPerBatch;
    int b  = blockIdx.x / blocksPerBatch;
    int r  = blockIdx.x - b * blocksPerBatch;
    int g  = r / chunksPerBatch;             // dim group 0..3
    int cc = r - g * chunksPerBatch;         // chunk index

    float4* s4 = (float4*)sacc;
    for (int i = tid; i < GDIMS * NNODES / 4; i += 256)
        s4[i] = make_float4(0.f, 0.f, 0.f, 0.f);
    __syncthreads();

    int flowBase = b * S + cc * CHUNK;

    // --- accumulate: one thread per flow per iteration ---
    for (int f0 = 0; f0 < CHUNK; f0 += 256) {
        int flow = flowBase + f0 + tid;
        int d = __ldg(&dst[flow]);
        const float4* fp = ff + (long)flow * (FD / 4) + g * (GDIMS / 4);
        float4 v0 = fp[0], v1 = fp[1], v2 = fp[2], v3 = fp[3];
        float* p = sacc + d;                 // + dim*NNODES
        atomicAdd(p + 0  * NNODES, v0.x); atomicAdd(p + 1  * NNODES, v0.y);
        atomicAdd(p + 2  * NNODES, v0.z); atomicAdd(p + 3  * NNODES, v0.w);
        atomicAdd(p + 4  * NNODES, v1.x); atomicAdd(p + 5  * NNODES, v1.y);
        atomicAdd(p + 6  * NNODES, v1.z); atomicAdd(p + 7  * NNODES, v1.w);
        atomicAdd(p + 8  * NNODES, v2.x); atomicAdd(p + 9  * NNODES, v2.y);
        atomicAdd(p + 10 * NNODES, v2.z); atomicAdd(p + 11 * NNODES, v2.w);
        atomicAdd(p + 12 * NNODES, v3.x); atomicAdd(p + 13 * NNODES, v3.y);
        atomicAdd(p + 14 * NNODES, v3.z); atomicAdd(p + 15 * NNODES, v3.w);
    }

    // --- adjacency: this block's 512-flow slice of the chunk ---
    int abase = flowBase + g * (CHUNK / NGRP);
    for (int i = tid; i < CHUNK / NGRP; i += 256) {
        int flow = abase + i;
        int d  = __ldg(&dst[flow]);
        int sI = __ldg(&src[flow]);
        atomicOr(&g_adj[(b * NNODES + sI) * 32 + (d  >> 5)], 1u << (d  & 31));
        atomicOr(&g_adj[(b * NNODES + d ) * 32 + (sI >> 5)], 1u << (sI & 31));
    }
    __syncthreads();

    // --- flush: per (node, j) read 4 dims, red.v4 if nonzero ---
    for (int i = tid; i < NNODES * (GDIMS / 4); i += 256) {
        int node = i & (NNODES - 1);
        int j    = i >> 10;                  // 0..3
        float x = sacc[(4 * j + 0) * NNODES + node];
        float y = sacc[(4 * j + 1) * NNODES + node];
        float z = sacc[(4 * j + 2) * NNODES + node];
        float w = sacc[(4 * j + 3) * NNODES + node];
        if (x != 0.f || y != 0.f || z != 0.f || w != 0.f) {
            float* p = &g_node[(long)(b * NNODES + node) * FD + g * GDIMS + j * 4];
            asm volatile("red.global.add.v4.f32 [%0], {%1,%2,%3,%4};"
                         :: "l"(p), "f"(x), "f"(y), "f"(z), "f"(w)
                         : "memory");
        }
    }
}

// ------------------------------------------------------------------
// K2: h = node / max(||node||,1e-12);  Wh = h @ W;  f1 = Wh·a1;  f2 = Wh·a2
// One warp per node; 8 warps per block; W cached in smem.
// Re-zeroes g_node after reading (restores launch invariant).
// ------------------------------------------------------------------
__global__ void k_nodeproc(const float* __restrict__ W,
                           const float* __restrict__ a1,
                           const float* __restrict__ a2,
                           int BN) {
    __shared__ float sW[FD * FD];
    __shared__ float sh[8][FD];
    int tid = threadIdx.x;
    for (int i = tid; i < FD * FD; i += 256) sW[i] = W[i];
    __syncthreads();

    int warp = tid >> 5, lane = tid & 31;
    int n = blockIdx.x * 8 + warp;
    if (n >= BN) return;

    float x0 = g_node[n * FD + lane];
    float x1 = g_node[n * FD + lane + 32];
    g_node[n * FD + lane]      = 0.0f;     // restore invariant
    g_node[n * FD + lane + 32] = 0.0f;

    float ss = x0 * x0 + x1 * x1;
    #pragma unroll
    for (int o = 16; o; o >>= 1) ss += __shfl_xor_sync(~0u, ss, o);
    float inv = 1.0f / fmaxf(sqrtf(ss), 1e-12f);

    sh[warp][lane]      = x0 * inv;
    sh[warp][lane + 32] = x1 * inv;
    __syncwarp();

    float w0 = 0.0f, w1 = 0.0f;
    #pragma unroll
    for (int d = 0; d < FD; d++) {
        float hd = sh[warp][d];
        w0 = fmaf(hd, sW[d * FD + lane],      w0);
        w1 = fmaf(hd, sW[d * FD + lane + 32], w1);
    }
    g_Wh[n * FD + lane]      = w0;
    g_Wh[n * FD + lane + 32] = w1;

    float p1 = w0 * a1[lane] + w1 * a1[lane + 32];
    float p2 = w0 * a2[lane] + w1 * a2[lane + 32];
    #pragma unroll
    for (int o = 16; o; o >>= 1) {
        p1 += __shfl_xor_sync(~0u, p1, o);
        p2 += __shfl_xor_sync(~0u, p2, o);
    }
    if (lane == 0) { g_f1[n] = p1; g_f2[n] = p2; }
}

// ------------------------------------------------------------------
// K3 (measured-best v2 structure + no-max single-exp + float4 AXPY):
// One block (128 thr) per row.
// ------------------------------------------------------------------
__global__ void k_attn(float4* __restrict__ out) {
    __shared__ short  s_jl[NNODES];
    __shared__ float  s_pv[NNODES];
    __shared__ float  s_red[4];
    __shared__ float4 s_acc[8][16];
    __shared__ int    s_cnt;

    int row = blockIdx.x;
    int b   = row >> 10;
    int tid = threadIdx.x;
    int warp = tid >> 5, lane = tid & 31;

    const float*  f2  = g_f2 + b * NNODES;
    const float4* Wh4 = (const float4*)(g_Wh + b * NNODES * FD);
    float f1i = g_f1[row];

    // --- compaction (warp 0) ---
    if (warp == 0) {
        unsigned word = g_adj[row * 32 + lane];
        g_adj[row * 32 + lane] = 0u;       // restore invariant
        int pc = __popc(word);
        int scan = pc;
        #pragma unroll
        for (int o = 1; o < 32; o <<= 1) {
            int v = __shfl_up_sync(~0u, scan, o);
            if (lane >= o) scan += v;
        }
        int excl = scan - pc;
        if (lane == 31) s_cnt = scan;
        int base = lane * 32;
        while (word) {
            int bp = __ffs(word) - 1;
            word &= word - 1;
            s_jl[excl++] = (short)(base + bp);
        }
    }
    __syncthreads();
    int cnt = s_cnt;

    int g = tid >> 4, sub = tid & 15;
    float4 acc = make_float4(0.0f, 0.0f, 0.0f, 0.0f);
    float scale;

    if (cnt == 0) {
        // fully masked row: uniform softmax -> mean of all Wh rows
        for (int j = g; j < NNODES; j += 8) {
            float4 v = Wh4[j * 16 + sub];
            acc.x += v.x; acc.y += v.y; acc.z += v.z; acc.w += v.w;
        }
        scale = 1.0f / NNODES;
    } else {
        // --- single pass: p = exp(leaky(e)) (no max subtraction:
        // logits O(10), fp32-exp-safe; masked entries exactly 0) ---
        float psum = 0.0f;
        for (int i = tid; i < cnt; i += 128) {
            int j = s_jl[i];
            float e = f1i + f2[j];
            e = e >= 0.0f ? e : 0.2f * e;
            float p = __expf(e);
            s_pv[i] = p;
            psum += p;
        }
        #pragma unroll
        for (int o = 16; o; o >>= 1) psum += __shfl_xor_sync(~0u, psum, o);
        if (lane == 0) s_red[warp] = psum;
        __syncthreads();
        float s = s_red[0] + s_red[1] + s_red[2] + s_red[3];

        // --- float4 AXPY over compacted list ---
        for (int i = g; i < cnt; i += 8) {
            int j   = s_jl[i];
            float p = s_pv[i];
            float4 v = Wh4[j * 16 + sub];
            acc.x = fmaf(p, v.x, acc.x);
            acc.y = fmaf(p, v.y, acc.y);
            acc.z = fmaf(p, v.z, acc.z);
            acc.w = fmaf(p, v.w, acc.w);
        }
        scale = 1.0f / s;
    }

    s_acc[g][sub] = acc;
    __syncthreads();
    if (tid < 16) {
        float4 r = s_acc[0][tid];
        #pragma unroll
        for (int gg = 1; gg < 8; gg++) {
            float4 v = s_acc[gg][tid];
            r.x += v.x; r.y += v.y; r.z += v.z; r.w += v.w;
        }
        r.x *= scale; r.y *= scale; r.z *= scale; r.w *= scale;
        r.x = r.x > 0.0f ? r.x : expm1f(r.x);
        r.y = r.y > 0.0f ? r.y : expm1f(r.y);
        r.z = r.z > 0.0f ? r.z : expm1f(r.z);
        r.w = r.w > 0.0f ? r.w : expm1f(r.w);
        out[row * 16 + tid] = r;
    }
}

// ------------------------------------------------------------------
extern "C" void kernel_launch(void* const* d_in, const int* in_sizes, int n_in,
                              void* d_out, int out_size) {
    const float* ff  = (const float*)d_in[0];
    const int*   src = (const int*)  d_in[1];
    const int*   dst = (const int*)  d_in[2];
    const float* W   = (const float*)d_in[9];
    const float* a1  = (const float*)d_in[10];
    const float* a2  = (const float*)d_in[11];

    int B = out_size / (NNODES * FD);       // 4
    int S = in_sizes[1] / B;                // 16384
    int BN = B * NNODES;

    int smemScatter = GDIMS * NNODES * sizeof(float);  // 64KB
    cudaFuncSetAttribute(k_scatter, cudaFuncAttributeMaxDynamicSharedMemorySize,
                         smemScatter);

    int nblk = B * NGRP * (S / CHUNK);      // 128
    k_scatter<<<nblk, 256, smemScatter>>>((const float4*)ff, src, dst, B, S);

    k_nodeproc<<<(BN + 7) / 8, 256>>>(W, a1, a2, BN);

    k_attn<<<BN, 128>>>((float4*)d_out);
}

// round 12
// speedup vs baseline: 1.3282x; 1.3282x over previous
#include <cuda_runtime.h>
#include <math.h>

#define NNODES 1024
#define FD 64
#define MAXB 4
#define CAP 64     // flows per (b,node) bucket; Poisson(16) -> P(>64) ~ 1e-18

// ---- scratch (no allocations allowed; statically zero-initialized) ----
// INVARIANT at every kernel_launch entry: g_cnt == 0, g_adj == 0.
// k_nodeproc re-zeroes g_cnt after reading; k_attn re-zeroes g_adj after
// reading. Invariant restored by the end of every launch.
__device__ int            g_cnt [MAXB * NNODES];           // flows with dst==node
__device__ unsigned short g_flow[MAXB * NNODES * CAP];     // flow-id within batch
__device__ float          g_Wh  [MAXB * NNODES * FD];      // Wh = normalize(node)@W
__device__ float          g_f1  [MAXB * NNODES];
__device__ float          g_f2  [MAXB * NNODES];
__device__ unsigned       g_adj [MAXB * NNODES * (NNODES/32)]; // adjacency bits

// ------------------------------------------------------------------
// K1: bin flows by dst + adjacency bitmask. One thread per flow.
// 131K counter atomics + 2M atomicOr (vs 4.2M red.v4 in the old scatter).
// ------------------------------------------------------------------
__global__ void k_build(const int* __restrict__ src,
                        const int* __restrict__ dst,
                        int B, int S) {
    int f = blockIdx.x * blockDim.x + threadIdx.x;
    if (f >= B * S) return;
    int b  = f / S;
    int sl = f - b * S;                     // flow index within batch (<16384)
    int d  = __ldg(&dst[f]);
    int s  = __ldg(&src[f]);

    int nd = b * NNODES + d;
    int p = atomicAdd(&g_cnt[nd], 1);
    if (p < CAP) g_flow[nd * CAP + p] = (unsigned short)sl;

    atomicOr(&g_adj[(b * NNODES + s) * 32 + (d >> 5)], 1u << (d & 31));
    atomicOr(&g_adj[nd * 32 + (s >> 5)], 1u << (s & 31));
}

// ------------------------------------------------------------------
// K2: gather node features + normalize + Wh = h@W + f1,f2.
// One warp per node; 8 warps/block; W cached in smem.
// Gather: lane = dim, ~16 independent coalesced 256B loads (MLP~16).
// Re-zeroes g_cnt after reading (restores launch invariant).
// ------------------------------------------------------------------
__global__ void k_nodeproc(const float* __restrict__ ff,
                           const float* __restrict__ W,
                           const float* __restrict__ a1,
                           const float* __restrict__ a2,
                           int BN, int S) {
    __shared__ float sW[FD * FD];
    __shared__ float sh[8][FD];
    int tid = threadIdx.x;
    for (int i = tid; i < FD * FD; i += 256) sW[i] = W[i];
    __syncthreads();

    int warp = tid >> 5, lane = tid & 31;
    int n = blockIdx.x * 8 + warp;
    if (n >= BN) return;

    int cnt = g_cnt[n];                     // broadcast load, all lanes
    if (lane == 0) g_cnt[n] = 0;            // restore invariant
    cnt = min(cnt, CAP);

    const unsigned short* lst = &g_flow[n * CAP];
    unsigned e0 = (lane      < cnt) ? lst[lane]      : 0u;
    unsigned e1 = (lane + 32 < cnt) ? lst[lane + 32] : 0u;
    int bbase = (n >> 10) * S * FD;         // float offset of this batch

    float x0 = 0.0f, x1 = 0.0f;
    for (int i = 0; i < cnt; i++) {
        int fl = __shfl_sync(~0u, (i < 32) ? e0 : e1, i & 31);
        const float* fp = ff + bbase + fl * FD;
        x0 += fp[lane];
        x1 += fp[lane + 32];
    }

    float ss = x0 * x0 + x1 * x1;
    #pragma unroll
    for (int o = 16; o; o >>= 1) ss += __shfl_xor_sync(~0u, ss, o);
    float inv = 1.0f / fmaxf(sqrtf(ss), 1e-12f);

    sh[warp][lane]      = x0 * inv;
    sh[warp][lane + 32] = x1 * inv;
    __syncwarp();

    float w0 = 0.0f, w1 = 0.0f;
    #pragma unroll
    for (int d = 0; d < FD; d++) {
        float hd = sh[warp][d];
        w0 = fmaf(hd, sW[d * FD + lane],      w0);
        w1 = fmaf(hd, sW[d * FD + lane + 32], w1);
    }
    g_Wh[n * FD + lane]      = w0;
    g_Wh[n * FD + lane + 32] = w1;

    float p1 = w0 * a1[lane] + w1 * a1[lane + 32];
    float p2 = w0 * a2[lane] + w1 * a2[lane + 32];
    #pragma unroll
    for (int o = 16; o; o >>= 1) {
        p1 += __shfl_xor_sync(~0u, p1, o);
        p2 += __shfl_xor_sync(~0u, p2, o);
    }
    if (lane == 0) { g_f1[n] = p1; g_f2[n] = p2; }
}

// ------------------------------------------------------------------
// K3 (measured-best structure, unchanged from R10):
// One block (128 thr) per row. Warp0 scan-compaction; single-exp pass
// (no max subtraction: logits O(10), fp32-exp-safe; masked entries are
// exactly 0 in the reference); one block sum; float4 AXPY.
// ------------------------------------------------------------------
__global__ void k_attn(float4* __restrict__ out) {
    __shared__ short  s_jl[NNODES];
    __shared__ float  s_pv[NNODES];
    __shared__ float  s_red[4];
    __shared__ float4 s_acc[8][16];
    __shared__ int    s_cnt;

    int row = blockIdx.x;
    int b   = row >> 10;
    int tid = threadIdx.x;
    int warp = tid >> 5, lane = tid & 31;

    const float*  f2  = g_f2 + b * NNODES;
    const float4* Wh4 = (const float4*)(g_Wh + b * NNODES * FD);
    float f1i = g_f1[row];

    // --- compaction (warp 0) ---
    if (warp == 0) {
        unsigned word = g_adj[row * 32 + lane];
        g_adj[row * 32 + lane] = 0u;       // restore invariant
        int pc = __popc(word);
        int scan = pc;
        #pragma unroll
        for (int o = 1; o < 32; o <<= 1) {
            int v = __shfl_up_sync(~0u, scan, o);
            if (lane >= o) scan += v;
        }
        int excl = scan - pc;
        if (lane == 31) s_cnt = scan;
        int base = lane * 32;
        while (word) {
            int bp = __ffs(word) - 1;
            word &= word - 1;
            s_jl[excl++] = (short)(base + bp);
        }
    }
    __syncthreads();
    int cnt = s_cnt;

    int g = tid >> 4, sub = tid & 15;
    float4 acc = make_float4(0.0f, 0.0f, 0.0f, 0.0f);
    float scale;

    if (cnt == 0) {
        // fully masked row: uniform softmax -> mean of all Wh rows
        for (int j = g; j < NNODES; j += 8) {
            float4 v = Wh4[j * 16 + sub];
            acc.x += v.x; acc.y += v.y; acc.z += v.z; acc.w += v.w;
        }
        scale = 1.0f / NNODES;
    } else {
        float psum = 0.0f;
        for (int i = tid; i < cnt; i += 128) {
            int j = s_jl[i];
            float e = f1i + f2[j];
            e = e >= 0.0f ? e : 0.2f * e;
            float p = __expf(e);
            s_pv[i] = p;
            psum += p;
        }
        #pragma unroll
        for (int o = 16; o; o >>= 1) psum += __shfl_xor_sync(~0u, psum, o);
        if (lane == 0) s_red[warp] = psum;
        __syncthreads();
        float s = s_red[0] + s_red[1] + s_red[2] + s_red[3];

        for (int i = g; i < cnt; i += 8) {
            int j   = s_jl[i];
            float p = s_pv[i];
            float4 v = Wh4[j * 16 + sub];
            acc.x = fmaf(p, v.x, acc.x);
            acc.y = fmaf(p, v.y, acc.y);
            acc.z = fmaf(p, v.z, acc.z);
            acc.w = fmaf(p, v.w, acc.w);
        }
        scale = 1.0f / s;
    }

    s_acc[g][sub] = acc;
    __syncthreads();
    if (tid < 16) {
        float4 r = s_acc[0][tid];
        #pragma unroll
        for (int gg = 1; gg < 8; gg++) {
            float4 v = s_acc[gg][tid];
            r.x += v.x; r.y += v.y; r.z += v.z; r.w += v.w;
        }
        r.x *= scale; r.y *= scale; r.z *= scale; r.w *= scale;
        r.x = r.x > 0.0f ? r.x : expm1f(r.x);
        r.y = r.y > 0.0f ? r.y : expm1f(r.y);
        r.z = r.z > 0.0f ? r.z : expm1f(r.z);
        r.w = r.w > 0.0f ? r.w : expm1f(r.w);
        out[row * 16 + tid] = r;
    }
}

// ------------------------------------------------------------------
extern "C" void kernel_launch(void* const* d_in, const int* in_sizes, int n_in,
                              void* d_out, int out_size) {
    const float* ff  = (const float*)d_in[0];
    const int*   src = (const int*)  d_in[1];
    const int*   dst = (const int*)  d_in[2];
    const float* W   = (const float*)d_in[9];
    const float* a1  = (const float*)d_in[10];
    const float* a2  = (const float*)d_in[11];

    int B = out_size / (NNODES * FD);       // 4
    int S = in_sizes[1] / B;                // 16384
    int BN = B * NNODES;

    int flows = B * S;
    k_build<<<(flows + 255) / 256, 256>>>(src, dst, B, S);

    k_nodeproc<<<(BN + 7) / 8, 256>>>(ff, W, a1, a2, BN, S);

    k_attn<<<BN, 128>>>((float4*)d_out);
}

// round 13
// speedup vs baseline: 1.3601x; 1.0240x over previous
#include <cuda_runtime.h>
#include <math.h>

#define NNODES 1024
#define FD 64
#define MAXB 4

// ---- scratch (no allocations allowed; statically zero-initialized) ----
// INVARIANT: g_node and g_adj are all-zero at every kernel_launch entry.
// k_nodeproc re-zeroes g_node after reading; k_attn re-zeroes g_adj after
// reading. So the invariant is restored by the end of every launch.
__device__ float    g_node[MAXB * NNODES * FD];          // scatter accumulator
__device__ float    g_Wh  [MAXB * NNODES * FD];          // Wh = normalize(node) @ W
__device__ float    g_f1  [MAXB * NNODES];
__device__ float    g_f2  [MAXB * NNODES];
__device__ unsigned g_adj [MAXB * NNODES * (NNODES/32)]; // adjacency bitmask

// ------------------------------------------------------------------
// K1 (R10, measured-best): scatter-add flow features at dst nodes +
// adjacency bitmask. One thread per (flow, 4-dim chunk).
// ------------------------------------------------------------------
__global__ void k_scatter(const float4* __restrict__ ff,
                          const int* __restrict__ src,
                          const int* __restrict__ dst,
                          int B, int S) {
    int t = blockIdx.x * blockDim.x + threadIdx.x;
    int total = B * S * 16;
    if (t >= total) return;
    int flow = t >> 4;
    int c    = t & 15;
    int b    = flow / S;
    int d    = __ldg(&dst[flow]);

    float4 v = ff[t];
    float* p = &g_node[(b * NNODES + d) * FD + c * 4];
    asm volatile("red.global.add.v4.f32 [%0], {%1,%2,%3,%4};"
                 :: "l"(p), "f"(v.x), "f"(v.y), "f"(v.z), "f"(v.w)
                 : "memory");

    if (c == 0) {
        int sI = __ldg(&src[flow]);
        atomicOr(&g_adj[(b * NNODES + sI) * 32 + (d  >> 5)], 1u << (d  & 31));
        atomicOr(&g_adj[(b * NNODES + d ) * 32 + (sI >> 5)], 1u << (sI & 31));
    }
}

// ------------------------------------------------------------------
// K2 (R10): h = node/||node||; Wh = h@W; f1 = Wh·a1; f2 = Wh·a2.
// One warp per node; re-zeroes g_node after reading.
// ------------------------------------------------------------------
__global__ void k_nodeproc(const float* __restrict__ W,
                           const float* __restrict__ a1,
                           const float* __restrict__ a2,
                           int BN) {
    __shared__ float sW[FD * FD];
    __shared__ float sh[8][FD];
    int tid = threadIdx.x;
    for (int i = tid; i < FD * FD; i += 256) sW[i] = W[i];
    __syncthreads();

    int warp = tid >> 5, lane = tid & 31;
    int n = blockIdx.x * 8 + warp;
    if (n >= BN) return;

    float x0 = g_node[n * FD + lane];
    float x1 = g_node[n * FD + lane + 32];
    g_node[n * FD + lane]      = 0.0f;     // restore invariant
    g_node[n * FD + lane + 32] = 0.0f;

    float ss = x0 * x0 + x1 * x1;
    #pragma unroll
    for (int o = 16; o; o >>= 1) ss += __shfl_xor_sync(~0u, ss, o);
    float inv = 1.0f / fmaxf(sqrtf(ss), 1e-12f);

    sh[warp][lane]      = x0 * inv;
    sh[warp][lane + 32] = x1 * inv;
    __syncwarp();

    float w0 = 0.0f, w1 = 0.0f;
    #pragma unroll
    for (int d = 0; d < FD; d++) {
        float hd = sh[warp][d];
        w0 = fmaf(hd, sW[d * FD + lane],      w0);
        w1 = fmaf(hd, sW[d * FD + lane + 32], w1);
    }
    g_Wh[n * FD + lane]      = w0;
    g_Wh[n * FD + lane + 32] = w1;

    float p1 = w0 * a1[lane] + w1 * a1[lane + 32];
    float p2 = w0 * a2[lane] + w1 * a2[lane + 32];
    #pragma unroll
    for (int o = 16; o; o >>= 1) {
        p1 += __shfl_xor_sync(~0u, p1, o);
        p2 += __shfl_xor_sync(~0u, p2, o);
    }
    if (lane == 0) { g_f1[n] = p1; g_f2[n] = p2; }
}

// ------------------------------------------------------------------
// K3 v6: one block (128 thr) per row. Warp0 FUSES compaction + p=exp
// (no max subtraction: logits O(10), fp32-exp-safe; masked entries are
// exactly 0 in the reference) + psum warp-reduction into the bit-walk.
// Then ONE sync -> float4 AXPY by all threads -> sync -> reduce/elu.
// 2 syncs, 1 list pass (was 3 syncs, 2 passes).
// ------------------------------------------------------------------
__global__ void __launch_bounds__(128, 8) k_attn(float4* __restrict__ out) {
    __shared__ short  s_jl[NNODES];
    __shared__ float  s_pv[NNODES];
    __shared__ float  s_psum;
    __shared__ float4 s_acc[8][16];
    __shared__ int    s_cnt;

    int row = blockIdx.x;
    int b   = row >> 10;
    int tid = threadIdx.x;
    int warp = tid >> 5, lane = tid & 31;

    const float*  f2  = g_f2 + b * NNODES;
    const float4* Wh4 = (const float4*)(g_Wh + b * NNODES * FD);

    // --- warp0: fused compaction + exp + partial-sum ---
    if (warp == 0) {
        float f1i = g_f1[row];
        unsigned word = g_adj[row * 32 + lane];
        g_adj[row * 32 + lane] = 0u;       // restore invariant
        int pc = __popc(word);
        int scan = pc;
        #pragma unroll
        for (int o = 1; o < 32; o <<= 1) {
            int v = __shfl_up_sync(~0u, scan, o);
            if (lane >= o) scan += v;
        }
        int excl = scan - pc;
        if (lane == 31) s_cnt = scan;
        int base = lane * 32;
        float psum = 0.0f;
        while (word) {
            int bp = __ffs(word) - 1;
            word &= word - 1;
            int j = base + bp;
            float e = f1i + f2[j];
            e = e >= 0.0f ? e : 0.2f * e;
            float p = __expf(e);
            s_jl[excl] = (short)j;
            s_pv[excl] = p;
            excl++;
            psum += p;
        }
        #pragma unroll
        for (int o = 16; o; o >>= 1) psum += __shfl_xor_sync(~0u, psum, o);
        if (lane == 0) s_psum = psum;
    }
    __syncthreads();
    int cnt = s_cnt;

    int g = tid >> 4, sub = tid & 15;
    float4 acc = make_float4(0.0f, 0.0f, 0.0f, 0.0f);
    float scale;

    if (cnt == 0) {
        // fully masked row: uniform softmax -> mean of all Wh rows
        for (int j = g; j < NNODES; j += 8) {
            float4 v = Wh4[j * 16 + sub];
            acc.x += v.x; acc.y += v.y; acc.z += v.z; acc.w += v.w;
        }
        scale = 1.0f / NNODES;
    } else {
        // --- float4 AXPY over compacted list, 8 groups x 16 threads ---
        for (int i = g; i < cnt; i += 8) {
            int j   = s_jl[i];
            float p = s_pv[i];
            float4 v = Wh4[j * 16 + sub];
            acc.x = fmaf(p, v.x, acc.x);
            acc.y = fmaf(p, v.y, acc.y);
            acc.z = fmaf(p, v.z, acc.z);
            acc.w = fmaf(p, v.w, acc.w);
        }
        scale = 1.0f / s_psum;
    }

    s_acc[g][sub] = acc;
    __syncthreads();
    if (tid < 16) {
        float4 r = s_acc[0][tid];
        #pragma unroll
        for (int gg = 1; gg < 8; gg++) {
            float4 v = s_acc[gg][tid];
            r.x += v.x; r.y += v.y; r.z += v.z; r.w += v.w;
        }
        r.x *= scale; r.y *= scale; r.z *= scale; r.w *= scale;
        r.x = r.x > 0.0f ? r.x : expm1f(r.x);
        r.y = r.y > 0.0f ? r.y : expm1f(r.y);
        r.z = r.z > 0.0f ? r.z : expm1f(r.z);
        r.w = r.w > 0.0f ? r.w : expm1f(r.w);
        out[row * 16 + tid] = r;
    }
}

// ------------------------------------------------------------------
extern "C" void kernel_launch(void* const* d_in, const int* in_sizes, int n_in,
                              void* d_out, int out_size) {
    const float* ff  = (const float*)d_in[0];
    const int*   src = (const int*)  d_in[1];
    const int*   dst = (const int*)  d_in[2];
    const float* W   = (const float*)d_in[9];
    const float* a1  = (const float*)d_in[10];
    const float* a2  = (const float*)d_in[11];

    int B = out_size / (NNODES * FD);       // 4
    int S = in_sizes[1] / B;                // 16384
    int BN = B * NNODES;

    int total = B * S * 16;
    k_scatter<<<(total + 255) / 256, 256>>>((const float4*)ff, src, dst, B, S);

    k_nodeproc<<<(BN + 7) / 8, 256>>>(W, a1, a2, BN);

    k_attn<<<BN, 128>>>((float4*)d_out);
}

// round 15
// speedup vs baseline: 1.5258x; 1.1218x over previous
#include <cuda_runtime.h>
#include <math.h>

#define NNODES 1024
#define FD 64
#define MAXB 4

// ---- scratch (no allocations allowed; statically zero-initialized) ----
// INVARIANT: g_node and g_adj are all-zero at every kernel_launch entry.
// k_nodeproc re-zeroes g_node after reading; k_attn re-zeroes g_adj after
// reading. So the invariant is restored by the end of every launch.
__device__ float    g_node[MAXB * NNODES * FD];          // scatter accumulator
__device__ float    g_Wh  [MAXB * NNODES * FD];          // Wh = normalize(node) @ W
__device__ float    g_f1  [MAXB * NNODES];
__device__ float    g_f2  [MAXB * NNODES];
__device__ unsigned g_adj [MAXB * NNODES * (NNODES/32)]; // adjacency bitmask

// ------------------------------------------------------------------
// K1 v2: scatter-add + adjacency. 8 threads per flow, each handling
// two float4s (c2 and c2+8: both lane-group-contiguous 128B segments).
// dst loaded once per flow (lane&7==0) and shfl-broadcast -> kills the
// 16x-redundant dst loads that made R10's scatter LSU-issue-bound.
// ------------------------------------------------------------------
__global__ void k_scatter(const float4* __restrict__ ff,
                          const int* __restrict__ src,
                          const int* __restrict__ dst,
                          int B, int S) {
    int t = blockIdx.x * blockDim.x + threadIdx.x;
    int total = B * S * 8;
    if (t >= total) return;
    int flow = t >> 3;
    int c2   = t & 7;                       // float4 pair selector
    int b    = flow / S;
    int lane = threadIdx.x & 31;

    int d = 0;
    if ((lane & 7) == 0) d = __ldg(&dst[flow]);
    d = __shfl_sync(~0u, d, lane & ~7);     // broadcast within 8-lane group

    const float4* fp = ff + (long)flow * 16;
    float4 v0 = fp[c2];
    float4 v1 = fp[c2 + 8];

    float* p = &g_node[(b * NNODES + d) * FD + c2 * 4];
    asm volatile("red.global.add.v4.f32 [%0], {%1,%2,%3,%4};"
                 :: "l"(p), "f"(v0.x), "f"(v0.y), "f"(v0.z), "f"(v0.w)
                 : "memory");
    asm volatile("red.global.add.v4.f32 [%0], {%1,%2,%3,%4};"
                 :: "l"(p + 32), "f"(v1.x), "f"(v1.y), "f"(v1.z), "f"(v1.w)
                 : "memory");

    if ((lane & 7) == 0 && c2 == 0) {
        int sI = __ldg(&src[flow]);
        atomicOr(&g_adj[(b * NNODES + sI) * 32 + (d  >> 5)], 1u << (d  & 31));
        atomicOr(&g_adj[(b * NNODES + d ) * 32 + (sI >> 5)], 1u << (sI & 31));
    }
}

// ------------------------------------------------------------------
// K2 (R10): h = node/||node||; Wh = h@W; f1 = Wh·a1; f2 = Wh·a2.
// One warp per node; re-zeroes g_node after reading.
// ------------------------------------------------------------------
__global__ void k_nodeproc(const float* __restrict__ W,
                           const float* __restrict__ a1,
                           const float* __restrict__ a2,
                           int BN) {
    __shared__ float sW[FD * FD];
    __shared__ float sh[8][FD];
    int tid = threadIdx.x;
    for (int i = tid; i < FD * FD; i += 256) sW[i] = W[i];
    __syncthreads();

    int warp = tid >> 5, lane = tid & 31;
    int n = blockIdx.x * 8 + warp;
    if (n >= BN) return;

    float x0 = g_node[n * FD + lane];
    float x1 = g_node[n * FD + lane + 32];
    g_node[n * FD + lane]      = 0.0f;     // restore invariant
    g_node[n * FD + lane + 32] = 0.0f;

    float ss = x0 * x0 + x1 * x1;
    #pragma unroll
    for (int o = 16; o; o >>= 1) ss += __shfl_xor_sync(~0u, ss, o);
    float inv = 1.0f / fmaxf(sqrtf(ss), 1e-12f);

    sh[warp][lane]      = x0 * inv;
    sh[warp][lane + 32] = x1 * inv;
    __syncwarp();

    float w0 = 0.0f, w1 = 0.0f;
    #pragma unroll
    for (int d = 0; d < FD; d++) {
        float hd = sh[warp][d];
        w0 = fmaf(hd, sW[d * FD + lane],      w0);
        w1 = fmaf(hd, sW[d * FD + lane + 32], w1);
    }
    g_Wh[n * FD + lane]      = w0;
    g_Wh[n * FD + lane + 32] = w1;

    float p1 = w0 * a1[lane] + w1 * a1[lane + 32];
    float p2 = w0 * a2[lane] + w1 * a2[lane + 32];
    #pragma unroll
    for (int o = 16; o; o >>= 1) {
        p1 += __shfl_xor_sync(~0u, p1, o);
        p2 += __shfl_xor_sync(~0u, p2, o);
    }
    if (lane == 0) { g_f1[n] = p1; g_f2[n] = p2; }
}

// ------------------------------------------------------------------
// K3 (R10 verbatim — measured local optimum; no launch-bounds cap):
// One block (128 thr) per row. Warp0 scan-compaction; single-exp pass
// (no max subtraction: logits O(10), fp32-exp-safe; masked entries are
// exactly 0 in the reference); one block sum; float4 AXPY.
// ------------------------------------------------------------------
__global__ void k_attn(float4* __restrict__ out) {
    __shared__ short  s_jl[NNODES];
    __shared__ float  s_pv[NNODES];
    __shared__ float  s_red[4];
    __shared__ float4 s_acc[8][16];
    __shared__ int    s_cnt;

    int row = blockIdx.x;
    int b   = row >> 10;
    int tid = threadIdx.x;
    int warp = tid >> 5, lane = tid & 31;

    const float*  f2  = g_f2 + b * NNODES;
    const float4* Wh4 = (const float4*)(g_Wh + b * NNODES * FD);
    float f1i = g_f1[row];

    // --- compaction (warp 0) ---
    if (warp == 0) {
        unsigned word = g_adj[row * 32 + lane];
        g_adj[row * 32 + lane] = 0u;       // restore invariant
        int pc = __popc(word);
        int scan = pc;
        #pragma unroll
        for (int o = 1; o < 32; o <<= 1) {
            int v = __shfl_up_sync(~0u, scan, o);
            if (lane >= o) scan += v;
        }
        int excl = scan - pc;
        if (lane == 31) s_cnt = scan;
        int base = lane * 32;
        while (word) {
            int bp = __ffs(word) - 1;
            word &= word - 1;
            s_jl[excl++] = (short)(base + bp);
        }
    }
    __syncthreads();
    int cnt = s_cnt;

    int g = tid >> 4, sub = tid & 15;
    float4 acc = make_float4(0.0f, 0.0f, 0.0f, 0.0f);
    float scale;

    if (cnt == 0) {
        // fully masked row: uniform softmax -> mean of all Wh rows
        for (int j = g; j < NNODES; j += 8) {
            float4 v = Wh4[j * 16 + sub];
            acc.x += v.x; acc.y += v.y; acc.z += v.z; acc.w += v.w;
        }
        scale = 1.0f / NNODES;
    } else {
        float psum = 0.0f;
        for (int i = tid; i < cnt; i += 128) {
            int j = s_jl[i];
            float e = f1i + f2[j];
            e = e >= 0.0f ? e : 0.2f * e;
            float p = __expf(e);
            s_pv[i] = p;
            psum += p;
        }
        #pragma unroll
        for (int o = 16; o; o >>= 1) psum += __shfl_xor_sync(~0u, psum, o);
        if (lane == 0) s_red[warp] = psum;
        __syncthreads();
        float s = s_red[0] + s_red[1] + s_red[2] + s_red[3];

        for (int i = g; i < cnt; i += 8) {
            int j   = s_jl[i];
            float p = s_pv[i];
            float4 v = Wh4[j * 16 + sub];
            acc.x = fmaf(p, v.x, acc.x);
            acc.y = fmaf(p, v.y, acc.y);
            acc.z = fmaf(p, v.z, acc.z);
            acc.w = fmaf(p, v.w, acc.w);
        }
        scale = 1.0f / s;
    }

    s_acc[g][sub] = acc;
    __syncthreads();
    if (tid < 16) {
        float4 r = s_acc[0][tid];
        #pragma unroll
        for (int gg = 1; gg < 8; gg++) {
            float4 v = s_acc[gg][tid];
            r.x += v.x; r.y += v.y; r.z += v.z; r.w += v.w;
        }
        r.x *= scale; r.y *= scale; r.z *= scale; r.w *= scale;
        r.x = r.x > 0.0f ? r.x : expm1f(r.x);
        r.y = r.y > 0.0f ? r.y : expm1f(r.y);
        r.z = r.z > 0.0f ? r.z : expm1f(r.z);
        r.w = r.w > 0.0f ? r.w : expm1f(r.w);
        out[row * 16 + tid] = r;
    }
}

// ------------------------------------------------------------------
extern "C" void kernel_launch(void* const* d_in, const int* in_sizes, int n_in,
                              void* d_out, int out_size) {
    const float* ff  = (const float*)d_in[0];
    const int*   src = (const int*)  d_in[1];
    const int*   dst = (const int*)  d_in[2];
    const float* W   = (const float*)d_in[9];
    const float* a1  = (const float*)d_in[10];
    const float* a2  = (const float*)d_in[11];

    int B = out_size / (NNODES * FD);       // 4
    int S = in_sizes[1] / B;                // 16384
    int BN = B * NNODES;

    int total = B * S * 8;
    k_scatter<<<(total + 255) / 256, 256>>>((const float4*)ff, src, dst, B, S);

    k_nodeproc<<<(BN + 7) / 8, 256>>>(W, a1, a2, BN);

    k_attn<<<BN, 128>>>((float4*)d_out);
}